// round 6
// baseline (speedup 1.0000x reference)
#include <cuda_runtime.h>
#include <cstdint>

// Problem constants
#define BB 256   // batch
#define TT 256   // time
#define DD 64    // input dim
#define HH 256   // hidden
#define GG 768   // 3*H gates

typedef unsigned long long ull;

// ---------------- scratch (static device memory; no allocations) ----------------
__device__ float  g_XT[TT * BB * DD];
__device__ float  g_H1[TT * BB * 2 * HH];
__device__ float  g_GI[2 * TT * BB * GG];
__device__ float4 g_WV0[2 * 4 * 3 * 64 * 64];      // [d][rank][g][k4][jloc] float4
__device__ float4 g_WV1[2 * 4 * 3 * 64 * 64];

// ---------------- helpers ----------------
__device__ __forceinline__ void fma2(ull &d, ull a, ull b) {
    asm volatile("fma.rn.f32x2 %0, %1, %2, %0;" : "+l"(d) : "l"(a), "l"(b));
}
__device__ __forceinline__ float hadd2(ull a) {
    float lo, hi;
    asm volatile("mov.b64 {%0, %1}, %2;" : "=f"(lo), "=f"(hi) : "l"(a));
    return lo + hi;
}
__device__ __forceinline__ float sigmoidf_fast(float x) {
    return 1.0f / (1.0f + __expf(-x));
}
__device__ __forceinline__ unsigned cvt_tf32(float f) {
    unsigned r;
    asm volatile("cvt.rna.tf32.f32 %0, %1;" : "=r"(r) : "f"(f));
    return r;
}
__device__ __forceinline__ unsigned mapa_sh(unsigned addr, unsigned rnk) {
    unsigned ra;
    asm volatile("mapa.shared::cluster.u32 %0, %1, %2;" : "=r"(ra) : "r"(addr), "r"(rnk));
    return ra;
}
#define CLUSTER_SYNC_() \
    asm volatile("barrier.cluster.arrive.aligned;\n\tbarrier.cluster.wait.aligned;" ::: "memory")

// ---------------- 0) no-op launch-order shim (puts scan0 at ncu's -s 5 slot) ----------------
__global__ void nudge_k() {}

// ---------------- 1) transpose x: (B,T,D) -> (T,B,D) ----------------
__global__ void transpose_x(const float* __restrict__ x) {
    int i = blockIdx.x * blockDim.x + threadIdx.x;
    if (i >= BB * TT * (DD / 4)) return;
    int d4 = i & 15;
    int t  = (i >> 4) & 255;
    int b  = i >> 12;
    const float4* src = reinterpret_cast<const float4*>(x);
    float4* dst = reinterpret_cast<float4*>(g_XT);
    dst[((t * BB + b) * (DD / 4)) + d4] = src[((b * TT + t) * (DD / 4)) + d4];
}

// ---------------- 2) shuffle w_hh to [d][rank][g][k4][jloc] float4 ----------------
__global__ void prep_whh(int layer, const float* __restrict__ w) {
    int i = blockIdx.x * blockDim.x + threadIdx.x;
    if (i >= 2 * 4 * 3 * 64 * 64) return;
    int jloc = i & 63;
    int k4   = (i >> 6) & 63;
    int rest = i >> 12;
    int g    = rest % 3;
    int dr   = rest / 3;
    int r    = dr & 3;
    int d    = dr >> 2;
    const float* src = w + ((size_t)(d * GG + g * 256 + r * 64 + jloc)) * HH + k4 * 4;
    float4 v = make_float4(src[0], src[1], src[2], src[3]);
    float4* dst = layer ? g_WV1 : g_WV0;
    dst[i] = v;
}

// ---------------- 3) gi GEMM: tf32x3 split-precision, 128x128 tiles ----------------
#define Bb_M 128
#define Bb_N 128
#define Bb_K 16
#define SSTR 20

__device__ __forceinline__ void mma_tf32(float* acc, const unsigned* a, unsigned b0, unsigned b1) {
    asm volatile(
        "mma.sync.aligned.m16n8k8.row.col.f32.tf32.tf32.f32 "
        "{%0,%1,%2,%3}, {%4,%5,%6,%7}, {%8,%9}, {%0,%1,%2,%3};\n"
        : "+f"(acc[0]), "+f"(acc[1]), "+f"(acc[2]), "+f"(acc[3])
        : "r"(a[0]), "r"(a[1]), "r"(a[2]), "r"(a[3]), "r"(b0), "r"(b1));
}

__global__ void __launch_bounds__(256) gemm_tf32(int layer,
                                                 const float* __restrict__ Wih,
                                                 const float* __restrict__ bih,
                                                 const float* __restrict__ bhh) {
    __shared__ float sA[2][Bb_M * SSTR];
    __shared__ float sB[2][Bb_N * SSTR];

    const float* A = layer ? g_H1 : g_XT;
    const int K    = layer ? 512 : 64;
    float* C = g_GI;

    int tid  = threadIdx.x;
    int m0   = blockIdx.x * Bb_M;
    int n0   = blockIdx.y * Bb_N;
    int d    = blockIdx.z;
    const float* Ab = A + (size_t)m0 * K;
    const float* Wb = Wih + ((size_t)d * GG + n0) * K;
    float* Cb = C + (size_t)d * (TT * BB) * GG;

    int lane = tid & 31, wid = tid >> 5;
    int wm = wid & 3, wn = wid >> 2;

    float acc[2][8][4];
#pragma unroll
    for (int a = 0; a < 2; a++)
#pragma unroll
        for (int b = 0; b < 8; b++)
#pragma unroll
            for (int c = 0; c < 4; c++) acc[a][b][c] = 0.0f;

    auto load_tile = [&](int kt, int buf) {
        int k0 = kt * Bb_K;
#pragma unroll
        for (int i = 0; i < 2; i++) {
            int s   = tid * 2 + i;
            int row = s >> 2;
            int seg = s & 3;
            unsigned da = (unsigned)__cvta_generic_to_shared(&sA[buf][row * SSTR + seg * 4]);
            const float* ga = Ab + (size_t)row * K + k0 + seg * 4;
            asm volatile("cp.async.cg.shared.global [%0], [%1], 16;\n" :: "r"(da), "l"(ga));
            unsigned db = (unsigned)__cvta_generic_to_shared(&sB[buf][row * SSTR + seg * 4]);
            const float* gb = Wb + (size_t)row * K + k0 + seg * 4;
            asm volatile("cp.async.cg.shared.global [%0], [%1], 16;\n" :: "r"(db), "l"(gb));
        }
        asm volatile("cp.async.commit_group;\n" ::: "memory");
    };

    const int KT = K / Bb_K;
    load_tile(0, 0);
    for (int kt = 0; kt < KT; kt++) {
        int buf = kt & 1;
        if (kt + 1 < KT) {
            load_tile(kt + 1, buf ^ 1);
            asm volatile("cp.async.wait_group 1;\n" ::: "memory");
        } else {
            asm volatile("cp.async.wait_group 0;\n" ::: "memory");
        }
        __syncthreads();
        const float* a_s = sA[buf];
        const float* b_s = sB[buf];
#pragma unroll
        for (int ks = 0; ks < 2; ks++) {
            int kk = ks * 8;
            unsigned ahi[2][4], alo[2][4];
#pragma unroll
            for (int mf = 0; mf < 2; mf++) {
                const float* p = a_s + (wm * 32 + mf * 16 + (lane >> 2)) * SSTR + kk + (lane & 3);
                float f0 = p[0];
                float f1 = p[8 * SSTR];
                float f2 = p[4];
                float f3 = p[8 * SSTR + 4];
                ahi[mf][0] = cvt_tf32(f0); alo[mf][0] = __float_as_uint(f0 - __uint_as_float(ahi[mf][0]));
                ahi[mf][1] = cvt_tf32(f1); alo[mf][1] = __float_as_uint(f1 - __uint_as_float(ahi[mf][1]));
                ahi[mf][2] = cvt_tf32(f2); alo[mf][2] = __float_as_uint(f2 - __uint_as_float(ahi[mf][2]));
                ahi[mf][3] = cvt_tf32(f3); alo[mf][3] = __float_as_uint(f3 - __uint_as_float(ahi[mf][3]));
            }
#pragma unroll
            for (int nf = 0; nf < 8; nf++) {
                const float* p = b_s + (wn * 64 + nf * 8 + (lane >> 2)) * SSTR + kk + (lane & 3);
                float g0 = p[0];
                float g1 = p[4];
                unsigned bhi0 = cvt_tf32(g0), blo0 = __float_as_uint(g0 - __uint_as_float(bhi0));
                unsigned bhi1 = cvt_tf32(g1), blo1 = __float_as_uint(g1 - __uint_as_float(bhi1));
#pragma unroll
                for (int mf = 0; mf < 2; mf++) {
                    mma_tf32(acc[mf][nf], ahi[mf], bhi0, bhi1);
                    mma_tf32(acc[mf][nf], ahi[mf], blo0, blo1);
                    mma_tf32(acc[mf][nf], alo[mf], bhi0, bhi1);
                }
            }
        }
        __syncthreads();
    }

#pragma unroll
    for (int mf = 0; mf < 2; mf++)
#pragma unroll
        for (int nf = 0; nf < 8; nf++)
#pragma unroll
            for (int i = 0; i < 4; i++) {
                int row = m0 + wm * 32 + mf * 16 + (lane >> 2) + ((i >> 1) ? 8 : 0);
                int col = n0 + wn * 64 + nf * 8 + (lane & 3) * 2 + (i & 1);
                float bias = __ldg(&bih[d * GG + col]) +
                             (col < 2 * HH ? __ldg(&bhh[d * GG + col]) : 0.0f);
                Cb[(size_t)row * GG + col] = acc[mf][nf][i] + bias;
            }
}

// ---------------- 4) GRU scan v2: 4-CTA cluster, weights read once-ish, 1 sync/step ----
// Threads: tid = bh*128 + j*2 + kh.  j in [0,64): hidden slice index (jg = rank*64+j).
//   kh in {0,1}: k-half (k4 in [kh*32, kh*32+32)) -> reduced by shfl_xor(1) (kh = lane bit 0).
//   bh in {0,1}: batch half (8 batches each).
// Weight smem [3][64 k4][64 j] u2 (196.6KB) read 2x/step (bh halves) = 3072 cyc crossbar.
// h double-buffered [2][16 b][64 slots] u2 (32KB); slot = (k4&31)*2 + (k4>>5) so the two
// kh lanes read adjacent 16B words. One cluster barrier per step (write next, read cur).
#define SMEM_W_BYTES  (3 * 64 * 64 * 16)      // 196608
#define SMEM_H_BYTES  (2 * 16 * 64 * 16)      // 32768
#define SMEM_SCAN     (SMEM_W_BYTES + SMEM_H_BYTES)

__global__ void __launch_bounds__(256, 1) __cluster_dims__(4, 1, 1)
gru_scan_cl(int layer, const float* __restrict__ bhh, float* __restrict__ fin) {
    extern __shared__ char smem[];
    ulonglong2* wv   = reinterpret_cast<ulonglong2*>(smem);                 // [3][64][64]
    char*       hreg = smem + SMEM_W_BYTES;                                  // 2 h buffers
    float*      hf   = reinterpret_cast<float*>(hreg);

    int tid  = threadIdx.x;
    int rank = blockIdx.x & 3;
    int cid  = blockIdx.x >> 2;
    int d    = cid & 1;
    int b0   = (cid >> 1) * 16;
    int kh   = tid & 1;
    int j    = (tid >> 1) & 63;
    int bh   = tid >> 7;
    int jg   = rank * 64 + j;

    // load weight slice (once)
    {
        const float4* wsrc = reinterpret_cast<const float4*>(layer ? g_WV1 : g_WV0)
                             + (size_t)(d * 4 + rank) * 12288;
        float4* wdst = reinterpret_cast<float4*>(smem);
#pragma unroll 8
        for (int i = tid; i < 12288; i += 256) wdst[i] = wsrc[i];
    }
    // zero both h buffers (8192 floats)
    for (int i = tid; i < 8192; i += 256) hf[i] = 0.0f;
    float bn = __ldg(&bhh[d * GG + 2 * HH + jg]);

    CLUSTER_SYNC_();

    // DSMEM bases of the h region in each cluster CTA
    unsigned hlocal = (unsigned)__cvta_generic_to_shared(hreg);
    unsigned ha0 = mapa_sh(hlocal, 0);
    unsigned ha1 = mapa_sh(hlocal, 1);
    unsigned ha2 = mapa_sh(hlocal, 2);
    unsigned ha3 = mapa_sh(hlocal, 3);

    // float index of element jg inside a batch row (slot permutation)
    int kj = jg >> 2;
    int pslot = ((kj & 31) * 2 + (kj >> 5)) * 4 + (jg & 3);

    float hn[8];
#pragma unroll
    for (int bi = 0; bi < 8; bi++) hn[bi] = 0.0f;

    for (int s = 0; s < TT; s++) {
        int t = d ? (TT - 1 - s) : s;

        // prefetch gi for this thread's 8 batches
        const float* gib = g_GI + ((size_t)d * (TT * BB) + (size_t)t * BB + b0 + bh * 8) * GG + jg;
        float gr[8], gz[8], gn[8];
#pragma unroll
        for (int bi = 0; bi < 8; bi++) {
            gr[bi] = __ldg(gib + (size_t)bi * GG);
            gz[bi] = __ldg(gib + (size_t)bi * GG + 256);
            gn[bi] = __ldg(gib + (size_t)bi * GG + 512);
        }

        const ulonglong2* hcur = reinterpret_cast<const ulonglong2*>(hreg + (s & 1) * 16384);
        const float*      hcurf = reinterpret_cast<const float*>(hcur);

        ull a0[8], a1[8], a2[8];
#pragma unroll
        for (int bi = 0; bi < 8; bi++) { a0[bi] = 0ull; a1[bi] = 0ull; a2[bi] = 0ull; }

#pragma unroll 4
        for (int i = 0; i < 32; i++) {
            int k4   = kh * 32 + i;
            int slot = i * 2 + kh;
            ulonglong2 wr = wv[0 * 4096 + k4 * 64 + j];
            ulonglong2 wz = wv[1 * 4096 + k4 * 64 + j];
            ulonglong2 wn = wv[2 * 4096 + k4 * 64 + j];
#pragma unroll
            for (int bi = 0; bi < 8; bi++) {
                ulonglong2 h = hcur[(bh * 8 + bi) * 64 + slot];
                fma2(a0[bi], h.x, wr.x); fma2(a0[bi], h.y, wr.y);
                fma2(a1[bi], h.x, wz.x); fma2(a1[bi], h.y, wz.y);
                fma2(a2[bi], h.x, wn.x); fma2(a2[bi], h.y, wn.y);
            }
        }

        // reduce kh pairs + gating (all 8 batches; store 4 selected by kh)
#pragma unroll
        for (int bi = 0; bi < 8; bi++) {
            float fr = hadd2(a0[bi]); fr += __shfl_xor_sync(0xFFFFFFFFu, fr, 1);
            float fz = hadd2(a1[bi]); fz += __shfl_xor_sync(0xFFFFFFFFu, fz, 1);
            float fn = hadd2(a2[bi]); fn += __shfl_xor_sync(0xFFFFFFFFu, fn, 1);
            float r = sigmoidf_fast(gr[bi] + fr);
            float z = sigmoidf_fast(gz[bi] + fz);
            float n = tanhf(gn[bi] + r * (fn + bn));
            float hold = hcurf[(bh * 8 + bi) * 256 + pslot];
            hn[bi] = n + z * (hold - n);
        }

        unsigned nboff = (unsigned)(((s & 1) ^ 1) * 16384) + (unsigned)pslot * 4u;
#pragma unroll
        for (int bi = 0; bi < 8; bi++) {
            if ((bi >> 2) == kh) {
                unsigned o = nboff + (unsigned)(bh * 8 + bi) * 1024u;
                float v = hn[bi];
                asm volatile("st.shared::cluster.f32 [%0], %1;" :: "r"(ha0 + o), "f"(v) : "memory");
                asm volatile("st.shared::cluster.f32 [%0], %1;" :: "r"(ha1 + o), "f"(v) : "memory");
                asm volatile("st.shared::cluster.f32 [%0], %1;" :: "r"(ha2 + o), "f"(v) : "memory");
                asm volatile("st.shared::cluster.f32 [%0], %1;" :: "r"(ha3 + o), "f"(v) : "memory");
                if (layer == 0) {
                    g_H1[((size_t)t * BB + b0 + bh * 8 + bi) * (2 * HH) + (size_t)d * HH + jg] = v;
                }
            }
        }

        CLUSTER_SYNC_();
    }

    if (layer != 0) {
#pragma unroll
        for (int bi = 0; bi < 8; bi++)
            if ((bi >> 2) == kh)
                fin[(size_t)(b0 + bh * 8 + bi) * (2 * HH) + (size_t)d * HH + jg] = hn[bi];
    }
}

// ---------------- launch ----------------
extern "C" void kernel_launch(void* const* d_in, const int* in_sizes, int n_in,
                              void* d_out, int out_size) {
    (void)in_sizes; (void)n_in; (void)out_size;
    const float* x     = (const float*)d_in[0];
    const float* w_ih0 = (const float*)d_in[1];
    const float* w_hh0 = (const float*)d_in[2];
    const float* b_ih0 = (const float*)d_in[3];
    const float* b_hh0 = (const float*)d_in[4];
    const float* w_ih1 = (const float*)d_in[5];
    const float* w_hh1 = (const float*)d_in[6];
    const float* b_ih1 = (const float*)d_in[7];
    const float* b_hh1 = (const float*)d_in[8];
    float* out = (float*)d_out;

    cudaFuncSetAttribute(gru_scan_cl, cudaFuncAttributeMaxDynamicSharedMemorySize, SMEM_SCAN);

    nudge_k<<<1, 1>>>();                                   // launch 0 (ncu shim)
    transpose_x<<<(BB * TT * (DD / 4) + 255) / 256, 256>>>(x);      // 1
    prep_whh<<<(2 * 4 * 3 * 64 * 64 + 255) / 256, 256>>>(0, w_hh0); // 2
    prep_whh<<<(2 * 4 * 3 * 64 * 64 + 255) / 256, 256>>>(1, w_hh1); // 3

    dim3 gg(512, 6, 2);
    gemm_tf32<<<gg, 256>>>(0, w_ih0, b_ih0, b_hh0);        // 4
    gru_scan_cl<<<128, 256, SMEM_SCAN>>>(0, b_hh0, nullptr); // 5  <- ncu -s 5 -c 1 lands here
    gemm_tf32<<<gg, 256>>>(1, w_ih1, b_ih1, b_hh1);        // 6
    gru_scan_cl<<<128, 256, SMEM_SCAN>>>(1, b_hh1, out);   // 7
}